// round 4
// baseline (speedup 1.0000x reference)
#include <cuda_runtime.h>
#include <math.h>

// ---------------------------------------------------------------------------
// CorrelationAdaptor: 4 levels. Per level:
//   corr(x[1], x[0]) -> offset = w_off @ corr -> deform conv 3x3 (dg=4) + ReLU
// S={64,32,16,8}, disp={8,8,4,2}, stride={2,1,1,1}
// K2={289,289,81,25}, pad=disp*stride={16,8,4,2}
// Output per level: [x[0] (2 imgs) ; feat (2 imgs)], 4*256*S*S floats.
// ---------------------------------------------------------------------------

// Scratch (__device__ globals; allocation-free rule)
__device__ float g_xt  [4 * 256 * 4096];   // NHWC x, reused per level: [tb][pix][c]
__device__ float g_corr[2 * 4096 * 292];   // [b][pix][SP] (SP >= K2, 16B-mult)
__device__ float g_off [2 * 4096 * 72];    // [b][pix][72]
__device__ float g_col [25067520];         // im2col all levels: 2*2304*(4096+1024+256+64)
__device__ float g_wp  [4 * 2304 * 256];   // weights K-major: [l][K][o], K=k*256+C

// ---------------------------------------------------------------------------
// NCHW -> NHWC transpose of one level's 4 images into g_xt.
// grid (P/32, 8, 4), block (32,8)
// ---------------------------------------------------------------------------
template<int S>
__global__ void transpose_kernel(const float* __restrict__ x) {
    constexpr int P = S * S;
    __shared__ float t[32][33];
    const float* src = x + (size_t)blockIdx.z * (256 * P);
    float* dst = g_xt + (size_t)blockIdx.z * (256 * P);
    int p0 = blockIdx.x * 32, c0 = blockIdx.y * 32;
    int tx = threadIdx.x;
    for (int j = threadIdx.y; j < 32; j += 8)
        t[j][tx] = src[(c0 + j) * P + (p0 + tx)];        // t[c_loc][p_loc]
    __syncthreads();
    for (int j = threadIdx.y; j < 32; j += 8)
        dst[(size_t)(p0 + j) * 256 + (c0 + tx)] = t[tx][j];
}

// ---------------------------------------------------------------------------
// Weight permute: w_adapt[o][C][ky][kx] (o*2304 + C*9 + k) -> g_wp[l][K][o],
// K = k*256 + C. Coalesced reads; scattered writes go through L2.
// grid (2304, 4), block 256
// ---------------------------------------------------------------------------
__global__ void wperm_kernel(const float* __restrict__ w0, const float* __restrict__ w1,
                             const float* __restrict__ w2, const float* __restrict__ w3) {
    int l = blockIdx.y;
    const float* src = (l == 0) ? w0 : (l == 1) ? w1 : (l == 2) ? w2 : w3;
    int t = blockIdx.x * 256 + threadIdx.x;   // [0, 589824)
    int o  = t / 2304;
    int ck = t - o * 2304;                    // C*9 + k
    int k = ck % 9;
    int C = ck / 9;
    g_wp[(size_t)l * (2304 * 256) + (size_t)(k * 256 + C) * 256 + o] = src[t];
}

// ---------------------------------------------------------------------------
// Correlation: warp per (b, pix). f1 = x[t=1,b] row in regs (8 floats/lane),
// loop shifts, load f2 row, dot, butterfly reduce, lane0 stores scalar.
// corr[b][pix][s] = dot/256, 0 if shift out of bounds (matches zero pad).
// block 128 (4 warps), grid 2*P/4
// ---------------------------------------------------------------------------
template<int S, int D, int ST, int PD, int K2, int SP>
__global__ void corr_kernel() {
    constexpr int P = S * S;
    int wid = (blockIdx.x * blockDim.x + threadIdx.x) >> 5;
    int lane = threadIdx.x & 31;
    if (wid >= 2 * P) return;
    int b = wid / P, pix = wid - b * P;
    int h = pix / S, w = pix - h * S;

    const float4* f1 = reinterpret_cast<const float4*>(
        g_xt + ((size_t)(2 + b) * P + pix) * 256 + lane * 8);
    float4 u0 = f1[0], u1 = f1[1];
    const float* f2b = g_xt + (size_t)b * P * 256;
    float* cw = g_corr + ((size_t)b * P + pix) * SP;

    int s = 0;
    for (int iy = 0; iy < D; iy++) {
        int py = h - PD + iy * ST;
        for (int ix = 0; ix < D; ix++, s++) {
            int px = w - PD + ix * ST;
            float v = 0.f;
            if ((unsigned)py < (unsigned)S && (unsigned)px < (unsigned)S) {
                const float4* f2 = reinterpret_cast<const float4*>(
                    f2b + ((size_t)py * S + px) * 256 + lane * 8);
                float4 q0 = f2[0], q1 = f2[1];
                v = u0.x * q0.x + u0.y * q0.y + u0.z * q0.z + u0.w * q0.w +
                    u1.x * q1.x + u1.y * q1.y + u1.z * q1.z + u1.w * q1.w;
            }
            v += __shfl_xor_sync(0xffffffffu, v, 16);
            v += __shfl_xor_sync(0xffffffffu, v, 8);
            v += __shfl_xor_sync(0xffffffffu, v, 4);
            v += __shfl_xor_sync(0xffffffffu, v, 2);
            v += __shfl_xor_sync(0xffffffffu, v, 1);
            if (lane == 0) cw[s] = v * (1.f / 256.f);
        }
    }
}

// ---------------------------------------------------------------------------
// Offset GEMM: block per (b,pix), 72 threads, one output row each.
// off[b][pix][o] = sum_s w_off[o][s] * corr[b][pix][s]
// grid 2*P, block 72
// ---------------------------------------------------------------------------
template<int P, int K2, int SP>
__global__ void offset_kernel(const float* __restrict__ w_off) {
    int bp = blockIdx.x;              // b*P + pix
    int o = threadIdx.x;              // 0..71
    const float* cr = g_corr + (size_t)bp * SP;
    const float* wr = w_off + (size_t)o * K2;
    float acc = 0.f;
    for (int s = 0; s < K2; s++) acc = fmaf(wr[s], cr[s], acc);
    g_off[(size_t)bp * 72 + o] = acc;
}

// ---------------------------------------------------------------------------
// Bilinear im2col: lane = pixel, warp handles one q=(g,k); 64 channels of
// group g via float4 over contiguous NHWC. Zero outside bounds (validity
// predicates fail safe on NaN/garbage: cvt->0x80000000 fails unsigned check).
// col[LB + (b*2304 + k*256 + g*64 + c)*P + pix]
// grid (P/32, 9, 2), block (32,4)
// ---------------------------------------------------------------------------
template<int S, int LB>
__global__ void im2col_kernel() {
    constexpr int P = S * S;
    int q = blockIdx.y * 4 + threadIdx.y;   // 0..35
    int g = q / 9, k = q - g * 9;
    int ky = k / 3, kx = k - ky * 3;
    int b = blockIdx.z;
    int pix = blockIdx.x * 32 + threadIdx.x;
    int h = pix / S, w = pix - h * S;

    const float* op = g_off + ((size_t)b * P + pix) * 72 + q * 2;
    float fy = (float)(h + ky - 1) + op[0];
    float fx = (float)(w + kx - 1) + op[1];
    float fy0 = floorf(fy), fx0 = floorf(fx);
    float wy = fy - fy0, wx = fx - fx0;
    int y0 = (int)fy0, x0 = (int)fx0;
    float w00 = (1.f - wy) * (1.f - wx);
    float w01 = (1.f - wy) * wx;
    float w10 = wy * (1.f - wx);
    float w11 = wy * wx;
    bool vy0 = (unsigned)y0 < (unsigned)S, vy1 = (unsigned)(y0 + 1) < (unsigned)S;
    bool vx0 = (unsigned)x0 < (unsigned)S, vx1 = (unsigned)(x0 + 1) < (unsigned)S;
    bool v00 = vy0 && vx0, v01 = vy0 && vx1, v10 = vy1 && vx0, v11 = vy1 && vx1;

    const float* xi = g_xt + (size_t)(2 + b) * P * 256 + g * 64;
    int i00 = (y0 * S + x0) * 256;

    float* cb = g_col + LB + ((size_t)b * 2304 + (size_t)k * 256 + g * 64) * P + pix;

#pragma unroll
    for (int c4 = 0; c4 < 16; c4++) {
        float ax = 0.f, ay = 0.f, az = 0.f, aw = 0.f;
        if (v00) { float4 u = *reinterpret_cast<const float4*>(xi + i00 + c4 * 4);
                   ax += w00 * u.x; ay += w00 * u.y; az += w00 * u.z; aw += w00 * u.w; }
        if (v01) { float4 u = *reinterpret_cast<const float4*>(xi + i00 + 256 + c4 * 4);
                   ax += w01 * u.x; ay += w01 * u.y; az += w01 * u.z; aw += w01 * u.w; }
        if (v10) { float4 u = *reinterpret_cast<const float4*>(xi + i00 + S * 256 + c4 * 4);
                   ax += w10 * u.x; ay += w10 * u.y; az += w10 * u.z; aw += w10 * u.w; }
        if (v11) { float4 u = *reinterpret_cast<const float4*>(xi + i00 + S * 256 + 256 + c4 * 4);
                   ax += w11 * u.x; ay += w11 * u.y; az += w11 * u.z; aw += w11 * u.w; }
        cb[(size_t)(c4 * 4 + 0) * P] = ax;
        cb[(size_t)(c4 * 4 + 1) * P] = ay;
        cb[(size_t)(c4 * 4 + 2) * P] = az;
        cb[(size_t)(c4 * 4 + 3) * P] = aw;
    }
}

// ---------------------------------------------------------------------------
// Batched GEMM over all levels/images: O[m][p] = relu(sum_K A[K][m] * B[K][p])
// A = g_wp[l] (K-major), B = g_col. 85 pixel tiles of 64 across levels,
// 2 M-tiles of 128, 2 images -> grid (85,2,2), block 256, 8x4 per thread.
// ---------------------------------------------------------------------------
__global__ void __launch_bounds__(256) gemm_kernel(float* __restrict__ out) {
    int t = blockIdx.x;
    int l, pt, HW, LB, OB;
    if (t < 64)      { l = 0; pt = t;      HW = 4096; LB = 0;        OB = 0;       }
    else if (t < 80) { l = 1; pt = t - 64; HW = 1024; LB = 18874368; OB = 4194304; }
    else if (t < 84) { l = 2; pt = t - 80; HW = 256;  LB = 23592960; OB = 5242880; }
    else             { l = 3; pt = t - 84; HW = 64;   LB = 24772608; OB = 5505024; }
    int n  = blockIdx.z;
    int m0 = blockIdx.y * 128;

    const float* A = g_wp + (size_t)l * (2304 * 256);
    const float* B = g_col + LB + (size_t)n * 2304 * HW + pt * 64;
    float* O = out + OB + ((size_t)(2 + n) * 256 + m0) * HW + pt * 64;

    __shared__ float As[16][128];
    __shared__ float Bs[16][64];

    int tid = threadIdx.x;
    int tx = tid & 15, ty = tid >> 4;          // tx: 4-px col group, ty: 8-row group
    int akk = tid >> 5;                        // 0..7
    int aoq = (tid & 31) * 4;                  // 0..124
    int bkk = tid >> 4;                        // 0..15
    int bpq = (tid & 15) * 4;                  // 0..60

    float acc[8][4];
#pragma unroll
    for (int i = 0; i < 8; i++)
#pragma unroll
        for (int j = 0; j < 4; j++) acc[i][j] = 0.f;

    for (int k0 = 0; k0 < 2304; k0 += 16) {
        float4 a0 = *reinterpret_cast<const float4*>(A + (size_t)(k0 + akk)     * 256 + m0 + aoq);
        float4 a1 = *reinterpret_cast<const float4*>(A + (size_t)(k0 + akk + 8) * 256 + m0 + aoq);
        float4 b0 = *reinterpret_cast<const float4*>(B + (size_t)(k0 + bkk) * HW + bpq);
        __syncthreads();
        *reinterpret_cast<float4*>(&As[akk][aoq])     = a0;
        *reinterpret_cast<float4*>(&As[akk + 8][aoq]) = a1;
        *reinterpret_cast<float4*>(&Bs[bkk][bpq])     = b0;
        __syncthreads();
#pragma unroll
        for (int kk = 0; kk < 16; kk++) {
            float4 A0 = *reinterpret_cast<float4*>(&As[kk][ty * 8]);
            float4 A1 = *reinterpret_cast<float4*>(&As[kk][ty * 8 + 4]);
            float4 B0 = *reinterpret_cast<float4*>(&Bs[kk][tx * 4]);
            float ar[8] = {A0.x, A0.y, A0.z, A0.w, A1.x, A1.y, A1.z, A1.w};
            float br[4] = {B0.x, B0.y, B0.z, B0.w};
#pragma unroll
            for (int i = 0; i < 8; i++)
#pragma unroll
                for (int j = 0; j < 4; j++) acc[i][j] += ar[i] * br[j];
        }
    }
#pragma unroll
    for (int i = 0; i < 8; i++) {
        float4 v = make_float4(fmaxf(acc[i][0], 0.f), fmaxf(acc[i][1], 0.f),
                               fmaxf(acc[i][2], 0.f), fmaxf(acc[i][3], 0.f));
        *reinterpret_cast<float4*>(O + (size_t)(ty * 8 + i) * HW + tx * 4) = v;
    }
}

// ---------------------------------------------------------------------------
// Per-level driver
// ---------------------------------------------------------------------------
template<int S, int D, int ST, int PD, int K2, int SP, int LB, int OUTOFF>
static void run_level(const float* x, const float* w_off, float* out) {
    constexpr int P = S * S;
    transpose_kernel<S><<<dim3(P / 32, 8, 4), dim3(32, 8)>>>(x);
    cudaMemcpyAsync(out + OUTOFF, x, (size_t)2 * 256 * P * sizeof(float),
                    cudaMemcpyDeviceToDevice);
    corr_kernel<S, D, ST, PD, K2, SP><<<2 * P / 4, 128>>>();
    offset_kernel<P, K2, SP><<<2 * P, 72>>>(w_off);
    im2col_kernel<S, LB><<<dim3(P / 32, 9, 2), dim3(32, 4)>>>();
}

extern "C" void kernel_launch(void* const* d_in, const int* in_sizes, int n_in,
                              void* d_out, int out_size) {
    // ----- Runtime input classification by element count (robust to the
    // metadata ordering: setup_inputs() interleaves w_off{i}/w_adapt{i}!) -----
    const float* xs[4]  = {0, 0, 0, 0};   // x0..x3 by size
    const float* wofs[4] = {0, 0, 0, 0};  // w_off0..3
    const float* wads[4] = {0, 0, 0, 0};  // w_adapt0..3
    int n_adapt = 0, n_off_big = 0;
    for (int i = 0; i < n_in; i++) {
        const float* p = (const float*)d_in[i];
        switch (in_sizes[i]) {
            case 4194304: xs[0] = p; break;                 // 2*2*256*64*64
            case 1048576: xs[1] = p; break;                 // 2*2*256*32*32
            case 262144:  xs[2] = p; break;                 // 2*2*256*16*16
            case 65536:   xs[3] = p; break;                 // 2*2*256*8*8
            case 589824:  wads[n_adapt++] = p; break;       // 256*256*3*3 (level order)
            case 20808:   wofs[n_off_big++] = p; break;     // 72*289 (levels 0,1 in order)
            case 5832:    wofs[2] = p; break;               // 72*81
            case 1800:    wofs[3] = p; break;               // 72*25
            default: break;
        }
    }
    float* out = (float*)d_out;

    wperm_kernel<<<dim3(2304, 4), 256>>>(wads[0], wads[1], wads[2], wads[3]);

    run_level<64, 17, 2, 16, 289, 292, 0,        0      >(xs[0], wofs[0], out);
    run_level<32, 17, 1,  8, 289, 292, 18874368, 4194304>(xs[1], wofs[1], out);
    run_level<16,  9, 1,  4,  81,  84, 23592960, 5242880>(xs[2], wofs[2], out);
    run_level< 8,  5, 1,  2,  25,  28, 24772608, 5505024>(xs[3], wofs[3], out);

    gemm_kernel<<<dim3(85, 2, 2), 256>>>(out);
}

// round 6
// speedup vs baseline: 1.2666x; 1.2666x over previous
#include <cuda_runtime.h>
#include <math.h>

// ---------------------------------------------------------------------------
// CorrelationAdaptor: 4 levels. Per level:
//   corr(x[1], x[0]) -> offset = w_off @ corr -> deform conv 3x3 (dg=4) + ReLU
// S={64,32,16,8}, disp={8,8,4,2}, stride={2,1,1,1}
// K2={289,289,81,25}, pad=disp*stride={16,8,4,2}, SP(padded)={320,320,96,32}
// ---------------------------------------------------------------------------

// Packed f32x2 helpers (Blackwell). All operands through b32/b64 int regs.
#define FMA_F32X2(acc, a, b) \
    asm("fma.rn.f32x2 %0, %1, %2, %0;" : "+l"(acc) : "l"(a), "l"(b))
#define PACK_F32X2(out, lo, hi) \
    asm("mov.b64 %0, {%1, %2};" : "=l"(out) : "r"(lo), "r"(hi))
#define UNPACK_F32X2(lo, hi, in) \
    asm("mov.b64 {%0, %1}, %2;" : "=r"(lo), "=r"(hi) : "l"(in))

// Scratch (__device__ globals; allocation-free rule)
__device__ float g_xt  [4 * 256 * 4096];   // NHWC x, reused per level: [tb][pix][c]
__device__ float g_corr[2 * 4096 * 320];   // [b][pix][SP], zero-padded to SP
__device__ float g_off [2 * 4096 * 72];    // [b][pix][72]
__device__ float g_col [25067520];         // im2col all levels: 2*2304*(4096+1024+256+64)
__device__ float g_wp  [4 * 2304 * 256];   // weights K-major: [l][K][o], K=k*256+C

// ---------------------------------------------------------------------------
// NCHW -> NHWC transpose of one level's 4 images into g_xt.
// ---------------------------------------------------------------------------
template<int S>
__global__ void transpose_kernel(const float* __restrict__ x) {
    constexpr int P = S * S;
    __shared__ float t[32][33];
    const float* src = x + (size_t)blockIdx.z * (256 * P);
    float* dst = g_xt + (size_t)blockIdx.z * (256 * P);
    int p0 = blockIdx.x * 32, c0 = blockIdx.y * 32;
    int tx = threadIdx.x;
    for (int j = threadIdx.y; j < 32; j += 8)
        t[j][tx] = src[(c0 + j) * P + (p0 + tx)];
    __syncthreads();
    for (int j = threadIdx.y; j < 32; j += 8)
        dst[(size_t)(p0 + j) * 256 + (c0 + tx)] = t[tx][j];
}

// ---------------------------------------------------------------------------
// Weight permute: w_adapt[o][C][ky][kx] -> g_wp[l][K][o], K = k*256 + C
// ---------------------------------------------------------------------------
__global__ void wperm_kernel(const float* __restrict__ w0, const float* __restrict__ w1,
                             const float* __restrict__ w2, const float* __restrict__ w3) {
    int l = blockIdx.y;
    const float* src = (l == 0) ? w0 : (l == 1) ? w1 : (l == 2) ? w2 : w3;
    int t = blockIdx.x * 256 + threadIdx.x;   // [0, 589824)
    int o  = t / 2304;
    int ck = t - o * 2304;                    // C*9 + k
    int k = ck % 9;
    int C = ck / 9;
    g_wp[(size_t)l * (2304 * 256) + (size_t)(k * 256 + C) * 256 + o] = src[t];
}

// ---------------------------------------------------------------------------
// Correlation: warp per (b, pix). f1 row in regs, loop shifts, dot+reduce.
// Writes corr[b][pix][s] = dot/256 (0 out of bounds), zero-pads s in [K2,SP).
// ---------------------------------------------------------------------------
template<int S, int D, int ST, int PD, int K2, int SP>
__global__ void corr_kernel() {
    constexpr int P = S * S;
    int wid = (blockIdx.x * blockDim.x + threadIdx.x) >> 5;
    int lane = threadIdx.x & 31;
    if (wid >= 2 * P) return;
    int b = wid / P, pix = wid - b * P;
    int h = pix / S, w = pix - h * S;

    const float4* f1 = reinterpret_cast<const float4*>(
        g_xt + ((size_t)(2 + b) * P + pix) * 256 + lane * 8);
    float4 u0 = f1[0], u1 = f1[1];
    const float* f2b = g_xt + (size_t)b * P * 256;
    float* cw = g_corr + ((size_t)b * P + pix) * SP;

    int s = 0;
    for (int iy = 0; iy < D; iy++) {
        int py = h - PD + iy * ST;
        for (int ix = 0; ix < D; ix++, s++) {
            int px = w - PD + ix * ST;
            float v = 0.f;
            if ((unsigned)py < (unsigned)S && (unsigned)px < (unsigned)S) {
                const float4* f2 = reinterpret_cast<const float4*>(
                    f2b + ((size_t)py * S + px) * 256 + lane * 8);
                float4 q0 = f2[0], q1 = f2[1];
                v = u0.x * q0.x + u0.y * q0.y + u0.z * q0.z + u0.w * q0.w +
                    u1.x * q1.x + u1.y * q1.y + u1.z * q1.z + u1.w * q1.w;
            }
            v += __shfl_xor_sync(0xffffffffu, v, 16);
            v += __shfl_xor_sync(0xffffffffu, v, 8);
            v += __shfl_xor_sync(0xffffffffu, v, 4);
            v += __shfl_xor_sync(0xffffffffu, v, 2);
            v += __shfl_xor_sync(0xffffffffu, v, 1);
            if (lane == 0) cw[s] = v * (1.f / 256.f);
        }
    }
    // zero-pad tail so chunked consumers never read garbage
    for (int z = K2 + lane; z < SP; z += 32) cw[z] = 0.f;
}

// ---------------------------------------------------------------------------
// Offset GEMM (tiled): block = 64 pixels x 72 outputs, 288 threads.
// Thread (og=tid/16, pg=tid%16) computes o=og*4+j (j<4), pix=pg+16*i (i<4).
// Per 32-chunk of s: Ws[s][o] (broadcast reads), Cs[s][px] (stride-1 reads).
// grid 2P/64, block 288
// ---------------------------------------------------------------------------
template<int P, int K2, int SP>
__global__ void __launch_bounds__(288) offset_kernel(const float* __restrict__ w_off) {
    __shared__ float Ws[32][73];
    __shared__ float Cs[32][65];
    int tid = threadIdx.x;
    int og = tid >> 4, pg = tid & 15;
    int pb = blockIdx.x * 64;                 // base pixel (bp index incl. b)

    float acc[4][4];
#pragma unroll
    for (int j = 0; j < 4; j++)
#pragma unroll
        for (int i = 0; i < 4; i++) acc[j][i] = 0.f;

    int wo = tid >> 2;                        // 0..71
    int ws0 = (tid & 3) * 8;                  // 0,8,16,24

    for (int cs = 0; cs < SP; cs += 32) {
        // stage w_off chunk: Ws[s][o]
#pragma unroll
        for (int u = 0; u < 8; u++) {
            int s = ws0 + u;
            int gs = cs + s;
            Ws[s][wo] = (gs < K2) ? w_off[(size_t)wo * K2 + gs] : 0.f;
        }
        // stage corr chunk transposed: Cs[s][px]
        for (int idx = tid; idx < 512; idx += 288) {
            int px = idx & 63, s4 = idx >> 6;   // s4: 0..7
            float4 v = *reinterpret_cast<const float4*>(
                g_corr + (size_t)(pb + px) * SP + cs + s4 * 4);
            Cs[s4 * 4 + 0][px] = v.x;
            Cs[s4 * 4 + 1][px] = v.y;
            Cs[s4 * 4 + 2][px] = v.z;
            Cs[s4 * 4 + 3][px] = v.w;
        }
        __syncthreads();
#pragma unroll 4
        for (int s = 0; s < 32; s++) {
            float c0 = Cs[s][pg];
            float c1 = Cs[s][pg + 16];
            float c2 = Cs[s][pg + 32];
            float c3 = Cs[s][pg + 48];
#pragma unroll
            for (int j = 0; j < 4; j++) {
                float wv = Ws[s][og * 4 + j];
                acc[j][0] = fmaf(wv, c0, acc[j][0]);
                acc[j][1] = fmaf(wv, c1, acc[j][1]);
                acc[j][2] = fmaf(wv, c2, acc[j][2]);
                acc[j][3] = fmaf(wv, c3, acc[j][3]);
            }
        }
        __syncthreads();
    }
#pragma unroll
    for (int i = 0; i < 4; i++)
#pragma unroll
        for (int j = 0; j < 4; j++)
            g_off[(size_t)(pb + pg + 16 * i) * 72 + og * 4 + j] = acc[j][i];
}

// ---------------------------------------------------------------------------
// Bilinear im2col: warp handles q=(g,k), lane = pixel.
// ---------------------------------------------------------------------------
template<int S, int LB>
__global__ void im2col_kernel() {
    constexpr int P = S * S;
    int q = blockIdx.y * 4 + threadIdx.y;   // 0..35
    int g = q / 9, k = q - g * 9;
    int ky = k / 3, kx = k - ky * 3;
    int b = blockIdx.z;
    int pix = blockIdx.x * 32 + threadIdx.x;
    int h = pix / S, w = pix - h * S;

    const float* op = g_off + ((size_t)b * P + pix) * 72 + q * 2;
    float fy = (float)(h + ky - 1) + op[0];
    float fx = (float)(w + kx - 1) + op[1];
    float fy0 = floorf(fy), fx0 = floorf(fx);
    float wy = fy - fy0, wx = fx - fx0;
    int y0 = (int)fy0, x0 = (int)fx0;
    float w00 = (1.f - wy) * (1.f - wx);
    float w01 = (1.f - wy) * wx;
    float w10 = wy * (1.f - wx);
    float w11 = wy * wx;
    bool vy0 = (unsigned)y0 < (unsigned)S, vy1 = (unsigned)(y0 + 1) < (unsigned)S;
    bool vx0 = (unsigned)x0 < (unsigned)S, vx1 = (unsigned)(x0 + 1) < (unsigned)S;
    bool v00 = vy0 && vx0, v01 = vy0 && vx1, v10 = vy1 && vx0, v11 = vy1 && vx1;

    const float* xi = g_xt + (size_t)(2 + b) * P * 256 + g * 64;
    int i00 = (y0 * S + x0) * 256;

    float* cb = g_col + LB + ((size_t)b * 2304 + (size_t)k * 256 + g * 64) * P + pix;

#pragma unroll
    for (int c4 = 0; c4 < 16; c4++) {
        float ax = 0.f, ay = 0.f, az = 0.f, aw = 0.f;
        if (v00) { float4 u = *reinterpret_cast<const float4*>(xi + i00 + c4 * 4);
                   ax += w00 * u.x; ay += w00 * u.y; az += w00 * u.z; aw += w00 * u.w; }
        if (v01) { float4 u = *reinterpret_cast<const float4*>(xi + i00 + 256 + c4 * 4);
                   ax += w01 * u.x; ay += w01 * u.y; az += w01 * u.z; aw += w01 * u.w; }
        if (v10) { float4 u = *reinterpret_cast<const float4*>(xi + i00 + S * 256 + c4 * 4);
                   ax += w10 * u.x; ay += w10 * u.y; az += w10 * u.z; aw += w10 * u.w; }
        if (v11) { float4 u = *reinterpret_cast<const float4*>(xi + i00 + S * 256 + 256 + c4 * 4);
                   ax += w11 * u.x; ay += w11 * u.y; az += w11 * u.z; aw += w11 * u.w; }
        cb[(size_t)(c4 * 4 + 0) * P] = ax;
        cb[(size_t)(c4 * 4 + 1) * P] = ay;
        cb[(size_t)(c4 * 4 + 2) * P] = az;
        cb[(size_t)(c4 * 4 + 3) * P] = aw;
    }
}

// ---------------------------------------------------------------------------
// Batched GEMM (FFMA2 + double buffer): O[m][p] = relu(sum_K A[K][m]*B[K][p])
// BM=128, BN=64, BK=16, 256 threads. Thread: 8 M (4 f32x2 pairs) x 4 N.
// grid (85, 2, 2)
// ---------------------------------------------------------------------------
__global__ void __launch_bounds__(256) gemm_kernel(float* __restrict__ out) {
    int t = blockIdx.x;
    int l, pt, HW, LB, OB;
    if (t < 64)      { l = 0; pt = t;      HW = 4096; LB = 0;        OB = 0;       }
    else if (t < 80) { l = 1; pt = t - 64; HW = 1024; LB = 18874368; OB = 4194304; }
    else if (t < 84) { l = 2; pt = t - 80; HW = 256;  LB = 23592960; OB = 5242880; }
    else             { l = 3; pt = t - 84; HW = 64;   LB = 24772608; OB = 5505024; }
    int n  = blockIdx.z;
    int m0 = blockIdx.y * 128;

    const float* A = g_wp + (size_t)l * (2304 * 256) + m0;
    const float* B = g_col + LB + (size_t)n * 2304 * HW + pt * 64;
    float* O = out + OB + ((size_t)(2 + n) * 256 + m0) * HW + pt * 64;

    __shared__ float As[2][16][128];
    __shared__ float Bs[2][16][64];

    int tid = threadIdx.x;
    int ty = tid >> 4, tx = tid & 15;
    int m0t = ty * 8, n0t = tx * 4;

    int ar = tid >> 5;                 // A stage rows ar, ar+8
    int ac = (tid & 31) * 4;
    int br = tid >> 4;                 // B stage row
    int bc = (tid & 15) * 4;

    unsigned long long acc[4][4];
    {
        unsigned z = 0u;
#pragma unroll
        for (int p = 0; p < 4; p++)
#pragma unroll
            for (int j = 0; j < 4; j++) PACK_F32X2(acc[p][j], z, z);
    }

    // preload stage 0
    {
        float4 a0 = *reinterpret_cast<const float4*>(A + (size_t)ar * 256 + ac);
        float4 a1 = *reinterpret_cast<const float4*>(A + (size_t)(ar + 8) * 256 + ac);
        float4 b0 = *reinterpret_cast<const float4*>(B + (size_t)br * HW + bc);
        *reinterpret_cast<float4*>(&As[0][ar][ac])     = a0;
        *reinterpret_cast<float4*>(&As[0][ar + 8][ac]) = a1;
        *reinterpret_cast<float4*>(&Bs[0][br][bc])     = b0;
    }
    __syncthreads();

    for (int tstep = 0; tstep < 144; tstep++) {
        int cur = tstep & 1;
        float4 a0, a1, b0;
        if (tstep + 1 < 144) {
            int k0 = (tstep + 1) * 16;
            a0 = *reinterpret_cast<const float4*>(A + (size_t)(k0 + ar) * 256 + ac);
            a1 = *reinterpret_cast<const float4*>(A + (size_t)(k0 + ar + 8) * 256 + ac);
            b0 = *reinterpret_cast<const float4*>(B + (size_t)(k0 + br) * HW + bc);
        }
#pragma unroll
        for (int kk = 0; kk < 16; kk++) {
            ulonglong2 ap0 = *reinterpret_cast<ulonglong2*>(&As[cur][kk][m0t]);
            ulonglong2 ap1 = *reinterpret_cast<ulonglong2*>(&As[cur][kk][m0t + 4]);
            float4 bv = *reinterpret_cast<float4*>(&Bs[cur][kk][n0t]);
            unsigned long long bs0, bs1, bs2, bs3;
            unsigned bxu = __float_as_uint(bv.x), byu = __float_as_uint(bv.y);
            unsigned bzu = __float_as_uint(bv.z), bwu = __float_as_uint(bv.w);
            PACK_F32X2(bs0, bxu, bxu);
            PACK_F32X2(bs1, byu, byu);
            PACK_F32X2(bs2, bzu, bzu);
            PACK_F32X2(bs3, bwu, bwu);
            FMA_F32X2(acc[0][0], ap0.x, bs0);
            FMA_F32X2(acc[0][1], ap0.x, bs1);
            FMA_F32X2(acc[0][2], ap0.x, bs2);
            FMA_F32X2(acc[0][3], ap0.x, bs3);
            FMA_F32X2(acc[1][0], ap0.y, bs0);
            FMA_F32X2(acc[1][1], ap0.y, bs1);
            FMA_F32X2(acc[1][2], ap0.y, bs2);
            FMA_F32X2(acc[1][3], ap0.y, bs3);
            FMA_F32X2(acc[2][0], ap1.x, bs0);
            FMA_F32X2(acc[2][1], ap1.x, bs1);
            FMA_F32X2(acc[2][2], ap1.x, bs2);
            FMA_F32X2(acc[2][3], ap1.x, bs3);
            FMA_F32X2(acc[3][0], ap1.y, bs0);
            FMA_F32X2(acc[3][1], ap1.y, bs1);
            FMA_F32X2(acc[3][2], ap1.y, bs2);
            FMA_F32X2(acc[3][3], ap1.y, bs3);
        }
        if (tstep + 1 < 144) {
            int nx = cur ^ 1;
            *reinterpret_cast<float4*>(&As[nx][ar][ac])     = a0;
            *reinterpret_cast<float4*>(&As[nx][ar + 8][ac]) = a1;
            *reinterpret_cast<float4*>(&Bs[nx][br][bc])     = b0;
        }
        __syncthreads();
    }

#pragma unroll
    for (int p = 0; p < 4; p++) {
        unsigned lo0, hi0, lo1, hi1, lo2, hi2, lo3, hi3;
        UNPACK_F32X2(lo0, hi0, acc[p][0]);
        UNPACK_F32X2(lo1, hi1, acc[p][1]);
        UNPACK_F32X2(lo2, hi2, acc[p][2]);
        UNPACK_F32X2(lo3, hi3, acc[p][3]);
        float4 r0 = make_float4(fmaxf(__uint_as_float(lo0), 0.f),
                                fmaxf(__uint_as_float(lo1), 0.f),
                                fmaxf(__uint_as_float(lo2), 0.f),
                                fmaxf(__uint_as_float(lo3), 0.f));
        float4 r1 = make_float4(fmaxf(__uint_as_float(hi0), 0.f),
                                fmaxf(__uint_as_float(hi1), 0.f),
                                fmaxf(__uint_as_float(hi2), 0.f),
                                fmaxf(__uint_as_float(hi3), 0.f));
        *reinterpret_cast<float4*>(O + (size_t)(m0t + 2 * p)     * HW + n0t) = r0;
        *reinterpret_cast<float4*>(O + (size_t)(m0t + 2 * p + 1) * HW + n0t) = r1;
    }
}

// ---------------------------------------------------------------------------
// Per-level driver
// ---------------------------------------------------------------------------
template<int S, int D, int ST, int PD, int K2, int SP, int LB, int OUTOFF>
static void run_level(const float* x, const float* w_off, float* out) {
    constexpr int P = S * S;
    transpose_kernel<S><<<dim3(P / 32, 8, 4), dim3(32, 8)>>>(x);
    cudaMemcpyAsync(out + OUTOFF, x, (size_t)2 * 256 * P * sizeof(float),
                    cudaMemcpyDeviceToDevice);
    corr_kernel<S, D, ST, PD, K2, SP><<<2 * P / 4, 128>>>();
    offset_kernel<P, K2, SP><<<2 * P / 64, 288>>>(w_off);
    im2col_kernel<S, LB><<<dim3(P / 32, 9, 2), dim3(32, 4)>>>();
}

extern "C" void kernel_launch(void* const* d_in, const int* in_sizes, int n_in,
                              void* d_out, int out_size) {
    // Runtime input classification by element count (metadata interleaves
    // w_off{i}/w_adapt{i} — do NOT trust signature order).
    const float* xs[4]   = {0, 0, 0, 0};
    const float* wofs[4] = {0, 0, 0, 0};
    const float* wads[4] = {0, 0, 0, 0};
    int n_adapt = 0, n_off_big = 0;
    for (int i = 0; i < n_in; i++) {
        const float* p = (const float*)d_in[i];
        switch (in_sizes[i]) {
            case 4194304: xs[0] = p; break;
            case 1048576: xs[1] = p; break;
            case 262144:  xs[2] = p; break;
            case 65536:   xs[3] = p; break;
            case 589824:  wads[n_adapt++] = p; break;
            case 20808:   wofs[n_off_big++] = p; break;
            case 5832:    wofs[2] = p; break;
            case 1800:    wofs[3] = p; break;
            default: break;
        }
    }
    float* out = (float*)d_out;

    wperm_kernel<<<dim3(2304, 4), 256>>>(wads[0], wads[1], wads[2], wads[3]);

    run_level<64, 17, 2, 16, 289, 320, 0,        0      >(xs[0], wofs[0], out);
    run_level<32, 17, 1,  8, 289, 320, 18874368, 4194304>(xs[1], wofs[1], out);
    run_level<16,  9, 1,  4,  81,  96, 23592960, 5242880>(xs[2], wofs[2], out);
    run_level< 8,  5, 1,  2,  25,  32, 24772608, 5505024>(xs[3], wofs[3], out);

    gemm_kernel<<<dim3(85, 2, 2), 256>>>(out);
}

// round 9
// speedup vs baseline: 1.6463x; 1.2998x over previous
#include <cuda_runtime.h>
#include <cuda_bf16.h>
#include <cstdint>
#include <math.h>

// ---------------------------------------------------------------------------
// CorrelationAdaptor: 4 levels. Per level:
//   corr(x[1], x[0]) -> offset = w_off @ corr -> deform conv 3x3 (dg=4) + ReLU
// S={64,32,16,8}, disp={8,8,4,2}, stride={2,1,1,1}
// K2={289,289,81,25}, pad={16,8,4,2}, SP(padded)={320,320,96,32}
// Deform conv = bilinear im2col (bf16 hi/lo split) + one mma.sync bf16 GEMM
// (3-term split: Ah*Bh + Ah*Bl + Al*Bh, fp32 accum) over a flat pixel space
// of 10880 pixels. Flat bases: L0:0 L1:8192 L2:10240 L3:10752.
// NOTE: harness compiles .target sm_100 (no 'a') -> tcgen05 unavailable;
// mma.sync/ldmatrix/cp.async are the supported tensor path.
// ---------------------------------------------------------------------------

// Scratch (__device__ globals; allocation-free rule)
__device__ float g_xt  [4 * 256 * 4096];                 // NHWC x per level
__device__ float g_corr[2 * 4096 * 320];                 // [b][pix][SP]
__device__ float g_off [2 * 4096 * 72];                  // [b][pix][72]
__device__ __align__(16) unsigned g_colh[10880 * 1152];  // bf16x2 col hi [p][K/2]
__device__ __align__(16) unsigned g_coll[10880 * 1152];  // bf16x2 col lo
__device__ __align__(16) unsigned g_wh  [4 * 256 * 1152];// bf16x2 W hi [l][o][K/2]
__device__ __align__(16) unsigned g_wl  [4 * 256 * 1152];// bf16x2 W lo

__device__ __forceinline__ uint32_t smem_u32(const void* p) {
    uint32_t a;
    asm("{ .reg .u64 t; cvta.to.shared.u64 t, %1; cvt.u32.u64 %0, t; }"
        : "=r"(a) : "l"(p));
    return a;
}

#define CPA16(dst, src) \
    asm volatile("cp.async.cg.shared.global [%0], [%1], 16;" \
                 :: "r"(dst), "l"(src))
#define CPA_COMMIT() asm volatile("cp.async.commit_group;" ::: "memory")
#define CPA_WAIT1()  asm volatile("cp.async.wait_group 1;" ::: "memory")
#define CPA_WAIT0()  asm volatile("cp.async.wait_group 0;" ::: "memory")

#define LDSM4(r, addr) \
    asm volatile("ldmatrix.sync.aligned.m8n8.x4.shared.b16 {%0,%1,%2,%3}, [%4];" \
                 : "=r"((r)[0]), "=r"((r)[1]), "=r"((r)[2]), "=r"((r)[3]) \
                 : "r"(addr))

#define MMA16816(c, a, b0, b1) \
    asm volatile("mma.sync.aligned.m16n8k16.row.col.f32.bf16.bf16.f32 " \
                 "{%0,%1,%2,%3}, {%4,%5,%6,%7}, {%8,%9}, {%0,%1,%2,%3};" \
                 : "+f"((c)[0]), "+f"((c)[1]), "+f"((c)[2]), "+f"((c)[3]) \
                 : "r"((a)[0]), "r"((a)[1]), "r"((a)[2]), "r"((a)[3]), \
                   "r"(b0), "r"(b1))

// ---------------------------------------------------------------------------
// NCHW -> NHWC transpose of one level's 4 images into g_xt.
// ---------------------------------------------------------------------------
template<int S>
__global__ void transpose_kernel(const float* __restrict__ x) {
    constexpr int P = S * S;
    __shared__ float t[32][33];
    const float* src = x + (size_t)blockIdx.z * (256 * P);
    float* dst = g_xt + (size_t)blockIdx.z * (256 * P);
    int p0 = blockIdx.x * 32, c0 = blockIdx.y * 32;
    int tx = threadIdx.x;
    for (int j = threadIdx.y; j < 32; j += 8)
        t[j][tx] = src[(c0 + j) * P + (p0 + tx)];
    __syncthreads();
    for (int j = threadIdx.y; j < 32; j += 8)
        dst[(size_t)(p0 + j) * 256 + (c0 + tx)] = t[tx][j];
}

// ---------------------------------------------------------------------------
// Weight prep: w_adapt[o][C][ky][kx] -> bf16 hi/lo in [l][o][K], K = k*256+C.
// ---------------------------------------------------------------------------
__global__ void wprep_kernel(const float* __restrict__ w0, const float* __restrict__ w1,
                             const float* __restrict__ w2, const float* __restrict__ w3) {
    int l = blockIdx.y;
    const float* src = (l == 0) ? w0 : (l == 1) ? w1 : (l == 2) ? w2 : w3;
    int idx = blockIdx.x * 256 + threadIdx.x;     // [0, 294912)
    int o = idx / 1152, j = idx - o * 1152;
    int K0 = 2 * j, K1 = K0 + 1;
    int k0 = K0 >> 8, C0 = K0 & 255;
    int k1 = K1 >> 8, C1 = K1 & 255;
    float a = src[o * 2304 + C0 * 9 + k0];
    float b = src[o * 2304 + C1 * 9 + k1];
    __nv_bfloat16 ah = __float2bfloat16_rn(a);
    __nv_bfloat16 bh = __float2bfloat16_rn(b);
    __nv_bfloat16 al = __float2bfloat16_rn(a - __bfloat162float(ah));
    __nv_bfloat16 bl = __float2bfloat16_rn(b - __bfloat162float(bh));
    size_t d = (size_t)l * 294912 + idx;
    g_wh[d] = ((unsigned)__bfloat16_as_ushort(bh) << 16) | __bfloat16_as_ushort(ah);
    g_wl[d] = ((unsigned)__bfloat16_as_ushort(bl) << 16) | __bfloat16_as_ushort(al);
}

// ---------------------------------------------------------------------------
// Correlation: warp per (b, pix).
// ---------------------------------------------------------------------------
template<int S, int D, int ST, int PD, int K2, int SP>
__global__ void corr_kernel() {
    constexpr int P = S * S;
    int wid = (blockIdx.x * blockDim.x + threadIdx.x) >> 5;
    int lane = threadIdx.x & 31;
    if (wid >= 2 * P) return;
    int b = wid / P, pix = wid - b * P;
    int h = pix / S, w = pix - h * S;

    const float4* f1 = reinterpret_cast<const float4*>(
        g_xt + ((size_t)(2 + b) * P + pix) * 256 + lane * 8);
    float4 u0 = f1[0], u1 = f1[1];
    const float* f2b = g_xt + (size_t)b * P * 256;
    float* cw = g_corr + ((size_t)b * P + pix) * SP;

    int s = 0;
    for (int iy = 0; iy < D; iy++) {
        int py = h - PD + iy * ST;
        for (int ix = 0; ix < D; ix++, s++) {
            int px = w - PD + ix * ST;
            float v = 0.f;
            if ((unsigned)py < (unsigned)S && (unsigned)px < (unsigned)S) {
                const float4* f2 = reinterpret_cast<const float4*>(
                    f2b + ((size_t)py * S + px) * 256 + lane * 8);
                float4 q0 = f2[0], q1 = f2[1];
                v = u0.x * q0.x + u0.y * q0.y + u0.z * q0.z + u0.w * q0.w +
                    u1.x * q1.x + u1.y * q1.y + u1.z * q1.z + u1.w * q1.w;
            }
            v += __shfl_xor_sync(0xffffffffu, v, 16);
            v += __shfl_xor_sync(0xffffffffu, v, 8);
            v += __shfl_xor_sync(0xffffffffu, v, 4);
            v += __shfl_xor_sync(0xffffffffu, v, 2);
            v += __shfl_xor_sync(0xffffffffu, v, 1);
            if (lane == 0) cw[s] = v * (1.f / 256.f);
        }
    }
    for (int z = K2 + lane; z < SP; z += 32) cw[z] = 0.f;
}

// ---------------------------------------------------------------------------
// Offset GEMM: block = 64 pixels x 72 outputs, 288 threads.
// ---------------------------------------------------------------------------
template<int P, int K2, int SP>
__global__ void __launch_bounds__(288) offset_kernel(const float* __restrict__ w_off) {
    __shared__ float Ws[32][73];
    __shared__ float Cs[32][65];
    int tid = threadIdx.x;
    int og = tid >> 4, pg = tid & 15;
    int pb = blockIdx.x * 64;

    float acc[4][4];
#pragma unroll
    for (int j = 0; j < 4; j++)
#pragma unroll
        for (int i = 0; i < 4; i++) acc[j][i] = 0.f;

    int wo = tid >> 2;
    int ws0 = (tid & 3) * 8;

    for (int cs = 0; cs < SP; cs += 32) {
#pragma unroll
        for (int u = 0; u < 8; u++) {
            int s = ws0 + u;
            int gs = cs + s;
            Ws[s][wo] = (gs < K2) ? w_off[(size_t)wo * K2 + gs] : 0.f;
        }
        for (int idx = tid; idx < 512; idx += 288) {
            int px = idx & 63, s4 = idx >> 6;
            float4 v = *reinterpret_cast<const float4*>(
                g_corr + (size_t)(pb + px) * SP + cs + s4 * 4);
            Cs[s4 * 4 + 0][px] = v.x;
            Cs[s4 * 4 + 1][px] = v.y;
            Cs[s4 * 4 + 2][px] = v.z;
            Cs[s4 * 4 + 3][px] = v.w;
        }
        __syncthreads();
#pragma unroll 4
        for (int s = 0; s < 32; s++) {
            float c0 = Cs[s][pg];
            float c1 = Cs[s][pg + 16];
            float c2 = Cs[s][pg + 32];
            float c3 = Cs[s][pg + 48];
#pragma unroll
            for (int j = 0; j < 4; j++) {
                float wv = Ws[s][og * 4 + j];
                acc[j][0] = fmaf(wv, c0, acc[j][0]);
                acc[j][1] = fmaf(wv, c1, acc[j][1]);
                acc[j][2] = fmaf(wv, c2, acc[j][2]);
                acc[j][3] = fmaf(wv, c3, acc[j][3]);
            }
        }
        __syncthreads();
    }
#pragma unroll
    for (int i = 0; i < 4; i++)
#pragma unroll
        for (int j = 0; j < 4; j++)
            g_off[(size_t)(pb + pg + 16 * i) * 72 + og * 4 + j] = acc[j][i];
}

// ---------------------------------------------------------------------------
// Bilinear im2col -> bf16 hi/lo rows [p][K], K = k*256 + C.
// ---------------------------------------------------------------------------
template<int S, int PB>
__global__ void im2col_kernel() {
    constexpr int P = S * S;
    int gw = (blockIdx.x * blockDim.x + threadIdx.x) >> 5;
    int lane = threadIdx.x & 31;
    int b = gw / P, pix = gw - b * P;
    int h = pix / S, w = pix - h * S;

    const float* op = g_off + (size_t)gw * 72;
    const float* xi = g_xt + (size_t)(2 + b) * P * 256;
    size_t rowb = (size_t)(PB + gw) * 1152;

    for (int q = 0; q < 36; q++) {
        int g = q / 9, k = q - g * 9;
        int ky = k / 3, kx = k - ky * 3;
        float fy = (float)(h + ky - 1) + op[q * 2];
        float fx = (float)(w + kx - 1) + op[q * 2 + 1];
        float fy0 = floorf(fy), fx0 = floorf(fx);
        float wy = fy - fy0, wx = fx - fx0;
        int y0 = (int)fy0, x0 = (int)fx0;
        float w00 = (1.f - wy) * (1.f - wx);
        float w01 = (1.f - wy) * wx;
        float w10 = wy * (1.f - wx);
        float w11 = wy * wx;
        bool vy0 = (unsigned)y0 < (unsigned)S, vy1 = (unsigned)(y0 + 1) < (unsigned)S;
        bool vx0 = (unsigned)x0 < (unsigned)S, vx1 = (unsigned)(x0 + 1) < (unsigned)S;
        bool v00 = vy0 && vx0, v01 = vy0 && vx1, v10 = vy1 && vx0, v11 = vy1 && vx1;

        const float* xc = xi + g * 64 + lane * 2;
        int i00 = (y0 * S + x0) * 256;
        float a0 = 0.f, a1 = 0.f;
        if (v00) { float2 u = *(const float2*)(xc + i00);
                   a0 += w00 * u.x; a1 += w00 * u.y; }
        if (v01) { float2 u = *(const float2*)(xc + i00 + 256);
                   a0 += w01 * u.x; a1 += w01 * u.y; }
        if (v10) { float2 u = *(const float2*)(xc + i00 + S * 256);
                   a0 += w10 * u.x; a1 += w10 * u.y; }
        if (v11) { float2 u = *(const float2*)(xc + i00 + S * 256 + 256);
                   a0 += w11 * u.x; a1 += w11 * u.y; }

        __nv_bfloat16 h0 = __float2bfloat16_rn(a0);
        __nv_bfloat16 h1 = __float2bfloat16_rn(a1);
        __nv_bfloat16 l0 = __float2bfloat16_rn(a0 - __bfloat162float(h0));
        __nv_bfloat16 l1 = __float2bfloat16_rn(a1 - __bfloat162float(h1));
        size_t d = rowb + k * 128 + g * 32 + lane;
        g_colh[d] = ((unsigned)__bfloat16_as_ushort(h1) << 16) | __bfloat16_as_ushort(h0);
        g_coll[d] = ((unsigned)__bfloat16_as_ushort(l1) << 16) | __bfloat16_as_ushort(l0);
    }
}

// ---------------------------------------------------------------------------
// mma.sync bf16 GEMM, 3-term split. CTA 128(M) x 64(N), 8 warps (32x32 each).
// K-chunks of 64 bf16, double-buffered cp.async staging.
// smem rows padded to 72 bf16 (144B = 9*16B -> conflict-free ldmatrix).
// Stage: Ah[128][72] Al[128][72] Bh[64][72] Bl[64][72] = 55296B; x2 = 110592B.
// grid (170, 2), block 256.
// ---------------------------------------------------------------------------
#define ST_SIZE 55296
#define OFF_AH  0
#define OFF_AL  18432
#define OFF_BH  36864
#define OFF_BL  46080
#define GEMM_SMEM 110592

__global__ void __launch_bounds__(256) gemm_mma(float* __restrict__ out) {
    extern __shared__ __align__(128) char smem[];
    uint32_t sb = smem_u32(smem);
    int tid = threadIdx.x;
    int lane = tid & 31, warp = tid >> 5;
    int warp_m = warp & 3, warp_n = warp >> 2;   // 4 x 2 warps

    int t = blockIdx.x, m0 = blockIdx.y * 128;
    int L, f, HW, OB, PBL;
    if (t < 128)      { L = 0; f = t * 64;         HW = 4096; OB = 0;       PBL = 0;     }
    else if (t < 160) { L = 1; f = (t - 128) * 64; HW = 1024; OB = 4194304; PBL = 8192;  }
    else if (t < 168) { L = 2; f = (t - 160) * 64; HW = 256;  OB = 5242880; PBL = 10240; }
    else              { L = 3; f = (t - 168) * 64; HW = 64;   OB = 5505024; PBL = 10752; }
    int p0 = PBL + f;
    int b = f / HW, pix = f - b * HW;

    const unsigned* GAh = g_wh + (size_t)(L * 256 + m0) * 1152;
    const unsigned* GAl = g_wl + (size_t)(L * 256 + m0) * 1152;
    const unsigned* GBh = g_colh + (size_t)p0 * 1152;
    const unsigned* GBl = g_coll + (size_t)p0 * 1152;

    // --- staging helper (ci: k-chunk, buf: stage) ---
    auto stage = [&](int ci, int buf) {
        uint32_t base = sb + buf * ST_SIZE;
        int kc = ci * 32;                       // u32 offset within row
#pragma unroll
        for (int i = 0; i < 4; i++) {
            int u = i * 256 + tid;              // [0,1024)
            int r = u >> 3, c = u & 7;
            uint32_t so = (uint32_t)(r * 144 + c * 16);
            CPA16(base + OFF_AH + so, GAh + (size_t)r * 1152 + kc + c * 4);
            CPA16(base + OFF_AL + so, GAl + (size_t)r * 1152 + kc + c * 4);
        }
#pragma unroll
        for (int i = 0; i < 2; i++) {
            int u = i * 256 + tid;              // [0,512)
            int r = u >> 3, c = u & 7;
            uint32_t so = (uint32_t)(r * 144 + c * 16);
            CPA16(base + OFF_BH + so, GBh + (size_t)r * 1152 + kc + c * 4);
            CPA16(base + OFF_BL + so, GBl + (size_t)r * 1152 + kc + c * 4);
        }
    };

    float acc[2][4][4];
#pragma unroll
    for (int am = 0; am < 2; am++)
#pragma unroll
        for (int an = 0; an < 4; an++)
#pragma unroll
            for (int i = 0; i < 4; i++) acc[am][an][i] = 0.f;

    // ldmatrix per-thread addresses (byte offsets within tile)
    uint32_t a_row = (uint32_t)(warp_m * 32 + (lane & 15));
    uint32_t a_koff = (uint32_t)((lane >> 4) * 16);          // k-half 16B
    uint32_t b_row = (uint32_t)(warp_n * 32 + (lane & 7) + ((lane >> 4) << 3));
    uint32_t b_koff = (uint32_t)(((lane >> 3) & 1) * 16);

    stage(0, 0);
    CPA_COMMIT();

    for (int ci = 0; ci < 36; ci++) {
        if (ci + 1 < 36) {
            stage(ci + 1, (ci + 1) & 1);
            CPA_COMMIT();
            CPA_WAIT1();
        } else {
            CPA_WAIT0();
        }
        __syncthreads();
        uint32_t base = sb + (ci & 1) * ST_SIZE;
#pragma unroll
        for (int ks = 0; ks < 4; ks++) {
            uint32_t ao = a_row * 144 + (uint32_t)(ks * 32) + a_koff;
            uint32_t bo = b_row * 144 + (uint32_t)(ks * 32) + b_koff;
            uint32_t ah0[4], ah1[4], al0[4], al1[4];
            uint32_t bh0[4], bh1[4], bl0[4], bl1[4];
            LDSM4(ah0, base + OFF_AH + ao);
            LDSM4(ah1, base + OFF_AH + ao + 16 * 144);
            LDSM4(al0, base + OFF_AL + ao);
            LDSM4(al1, base + OFF_AL + ao + 16 * 144);
            LDSM4(bh0, base + OFF_BH + bo);
            LDSM4(bh1, base + OFF_BH + bo + 16 * 144);
            LDSM4(bl0, base + OFF_BL + bo);
            LDSM4(bl1, base + OFF_BL + bo + 16 * 144);

            // hh
            MMA16816(acc[0][0], ah0, bh0[0], bh0[1]);
            MMA16816(acc[0][1], ah0, bh0[2], bh0[3]);
            MMA16816(acc[0][2], ah0, bh1[0], bh1[1]);
            MMA16816(acc[0][3], ah0, bh1[2], bh1[3]);
            MMA16816(acc[1][0], ah1, bh0[0], bh0[1]);
            MMA16816(acc[1][1], ah1, bh0[2], bh0[3]);
            MMA16816(acc[1][2], ah1, bh1[0], bh1[1]);
            MMA16816(acc[1][3], ah1, bh1[2], bh1[3]);
            // hl
            MMA16816(acc[0][0], ah0, bl0[0], bl0[1]);
            MMA16816(acc[0][1], ah0, bl0[2], bl0[3]);
            MMA16816(acc[0][2], ah0, bl1[0], bl1[1]);
            MMA16816(acc[0][3], ah0, bl1[2], bl1[3]);
            MMA16816(acc[1][0], ah1, bl0[0], bl0[1]);
            MMA16816(acc[1][1], ah1, bl0[2], bl0[3]);
            MMA16816(acc[1][2], ah1, bl1[0], bl1[1]);
            MMA16816(acc[1][3], ah1, bl1[2], bl1[3]);
            // lh
            MMA16816(acc[0][0], al0, bh0[0], bh0[1]);
            MMA16816(acc[0][1], al0, bh0[2], bh0[3]);
            MMA16816(acc[0][2], al0, bh1[0], bh1[1]);
            MMA16816(acc[0][3], al0, bh1[2], bh1[3]);
            MMA16816(acc[1][0], al1, bh0[0], bh0[1]);
            MMA16816(acc[1][1], al1, bh0[2], bh0[3]);
            MMA16816(acc[1][2], al1, bh1[0], bh1[1]);
            MMA16816(acc[1][3], al1, bh1[2], bh1[3]);
        }
        __syncthreads();
    }

    // epilogue: ReLU + store. C frag: c0,c1 -> row lane/4, cols 2*(lane%4)(+1);
    // c2,c3 -> row lane/4 + 8.
    float* Ob = out + OB + ((size_t)(2 + b) * 256) * HW + pix;
#pragma unroll
    for (int am = 0; am < 2; am++) {
        int o = m0 + warp_m * 32 + am * 16 + (lane >> 2);
#pragma unroll
        for (int an = 0; an < 4; an++) {
            int c = warp_n * 32 + an * 8 + (lane & 3) * 2;
            float2 v0 = make_float2(fmaxf(acc[am][an][0], 0.f),
                                    fmaxf(acc[am][an][1], 0.f));
            float2 v1 = make_float2(fmaxf(acc[am][an][2], 0.f),
                                    fmaxf(acc[am][an][3], 0.f));
            *reinterpret_cast<float2*>(Ob + (size_t)o * HW + c) = v0;
            *reinterpret_cast<float2*>(Ob + (size_t)(o + 8) * HW + c) = v1;
        }
    }
}

// ---------------------------------------------------------------------------
// Per-level driver
// ---------------------------------------------------------------------------
template<int S, int D, int ST, int PD, int K2, int SP, int PB, int OUTOFF>
static void run_level(const float* x, const float* w_off, float* out) {
    constexpr int P = S * S;
    transpose_kernel<S><<<dim3(P / 32, 8, 4), dim3(32, 8)>>>(x);
    cudaMemcpyAsync(out + OUTOFF, x, (size_t)2 * 256 * P * sizeof(float),
                    cudaMemcpyDeviceToDevice);
    corr_kernel<S, D, ST, PD, K2, SP><<<2 * P / 4, 128>>>();
    offset_kernel<P, K2, SP><<<2 * P / 64, 288>>>(w_off);
    im2col_kernel<S, PB><<<2 * P / 4, 128>>>();
}

extern "C" void kernel_launch(void* const* d_in, const int* in_sizes, int n_in,
                              void* d_out, int out_size) {
    // Runtime input classification by element count (metadata interleaves
    // w_off{i}/w_adapt{i} — do NOT trust signature order).
    const float* xs[4]   = {0, 0, 0, 0};
    const float* wofs[4] = {0, 0, 0, 0};
    const float* wads[4] = {0, 0, 0, 0};
    int n_adapt = 0, n_off_big = 0;
    for (int i = 0; i < n_in; i++) {
        const float* p = (const float*)d_in[i];
        switch (in_sizes[i]) {
            case 4194304: xs[0] = p; break;
            case 1048576: xs[1] = p; break;
            case 262144:  xs[2] = p; break;
            case 65536:   xs[3] = p; break;
            case 589824:  wads[n_adapt++] = p; break;
            case 20808:   wofs[n_off_big++] = p; break;
            case 5832:    wofs[2] = p; break;
            case 1800:    wofs[3] = p; break;
            default: break;
        }
    }
    float* out = (float*)d_out;

    cudaFuncSetAttribute(gemm_mma, cudaFuncAttributeMaxDynamicSharedMemorySize,
                         GEMM_SMEM);

    wprep_kernel<<<dim3(1152, 4), 256>>>(wads[0], wads[1], wads[2], wads[3]);

    run_level<64, 17, 2, 16, 289, 320, 0,     0      >(xs[0], wofs[0], out);
    run_level<32, 17, 1,  8, 289, 320, 8192,  4194304>(xs[1], wofs[1], out);
    run_level<16,  9, 1,  4,  81,  96, 10240, 5242880>(xs[2], wofs[2], out);
    run_level< 8,  5, 1,  2,  25,  32, 10752, 5505024>(xs[3], wofs[3], out);

    gemm_mma<<<dim3(170, 2), 256, GEMM_SMEM>>>(out);
}

// round 12
// speedup vs baseline: 2.1202x; 1.2878x over previous
#include <cuda_runtime.h>
#include <cuda_bf16.h>
#include <cstdint>
#include <math.h>

// ---------------------------------------------------------------------------
// CorrelationAdaptor, fully batched: 6 launches total.
//   wprep -> transpose_all(+copy) -> corr_all -> offset_all -> im2col_all
//   -> gemm_mma (mma.sync bf16 3-term split)
// Levels: S={64,32,16,8}, disp={8,8,4,2}, stride={2,1,1,1}
// K2={289,289,81,25}, pad={16,8,4,2}, SP={320,320,96,32}
// Flat pixel space (2P per level): bases {0, 8192, 10240, 10752}, total 10880.
// g_xt bases {0, 4194304, 5242880, 5505024}; g_corr bases {0, 2621440,
// 3276800, 3325952}; out level bases {0, 4194304, 5242880, 5505024}.
// NOTE: harness compiles .target sm_100 (no 'a') -> tcgen05 unavailable.
// ---------------------------------------------------------------------------

__device__ float g_xt  [5570560];                        // NHWC x, all levels
__device__ float g_corr[3330048];                        // [flat bp][SP]
__device__ float g_off [10880 * 72];                     // [flat p][72]
__device__ __align__(16) unsigned g_colh[10880 * 1152];  // bf16x2 col hi [p][K/2]
__device__ __align__(16) unsigned g_coll[10880 * 1152];  // bf16x2 col lo
__device__ __align__(16) unsigned g_wh  [4 * 256 * 1152];// bf16x2 W hi [l][o][K/2]
__device__ __align__(16) unsigned g_wl  [4 * 256 * 1152];// bf16x2 W lo

__device__ __forceinline__ uint32_t smem_u32(const void* p) {
    uint32_t a;
    asm("{ .reg .u64 t; cvta.to.shared.u64 t, %1; cvt.u32.u64 %0, t; }"
        : "=r"(a) : "l"(p));
    return a;
}

#define CPA16(dst, src) \
    asm volatile("cp.async.cg.shared.global [%0], [%1], 16;" \
                 :: "r"(dst), "l"(src))
#define CPA_COMMIT() asm volatile("cp.async.commit_group;" ::: "memory")
#define CPA_WAIT1()  asm volatile("cp.async.wait_group 1;" ::: "memory")
#define CPA_WAIT0()  asm volatile("cp.async.wait_group 0;" ::: "memory")

#define LDSM4(r, addr) \
    asm volatile("ldmatrix.sync.aligned.m8n8.x4.shared.b16 {%0,%1,%2,%3}, [%4];" \
                 : "=r"((r)[0]), "=r"((r)[1]), "=r"((r)[2]), "=r"((r)[3]) \
                 : "r"(addr))

#define MMA16816(c, a, b0, b1) \
    asm volatile("mma.sync.aligned.m16n8k16.row.col.f32.bf16.bf16.f32 " \
                 "{%0,%1,%2,%3}, {%4,%5,%6,%7}, {%8,%9}, {%0,%1,%2,%3};" \
                 : "+f"((c)[0]), "+f"((c)[1]), "+f"((c)[2]), "+f"((c)[3]) \
                 : "r"((a)[0]), "r"((a)[1]), "r"((a)[2]), "r"((a)[3]), \
                   "r"(b0), "r"(b1))

// ---------------------------------------------------------------------------
// transpose_all: NCHW -> NHWC for all levels; folds the x[0] passthrough copy
// (tb < 2) into the same kernel. Flat grid 5440 blocks of (32,8).
// Per level: (P/32) p-tiles x 8 c-tiles x 4 tb => local = (pt*8 + ct)*4 + tb.
// ---------------------------------------------------------------------------
template<int S>
__device__ __forceinline__ void transpose_one(
    int local, const float* __restrict__ x, float* __restrict__ xtb,
    float* __restrict__ outb, float (*t)[33]) {
    constexpr int P = S * S;
    int tb = local & 3;
    int ct = (local >> 2) & 7;
    int pt = local >> 5;
    int p0 = pt * 32, c0 = ct * 32;
    const float* src = x + (size_t)tb * (256 * P);
    float* dst = xtb + (size_t)tb * (256 * P);
    int tx = threadIdx.x;
    bool copy = (tb < 2);
    float* cp = outb + (size_t)tb * (256 * P);
    for (int j = threadIdx.y; j < 32; j += 8) {
        float v = src[(c0 + j) * P + (p0 + tx)];
        t[j][tx] = v;
        if (copy) cp[(c0 + j) * P + (p0 + tx)] = v;
    }
    __syncthreads();
    for (int j = threadIdx.y; j < 32; j += 8)
        dst[(size_t)(p0 + j) * 256 + (c0 + tx)] = t[tx][j];
}

__global__ void transpose_all(const float* __restrict__ x0, const float* __restrict__ x1,
                              const float* __restrict__ x2, const float* __restrict__ x3,
                              float* __restrict__ out) {
    __shared__ float t[32][33];
    int id = blockIdx.x;
    if (id < 4096)      transpose_one<64>(id,        x0, g_xt,           out,           t);
    else if (id < 5120) transpose_one<32>(id - 4096, x1, g_xt + 4194304, out + 4194304, t);
    else if (id < 5376) transpose_one<16>(id - 5120, x2, g_xt + 5242880, out + 5242880, t);
    else                transpose_one< 8>(id - 5376, x3, g_xt + 5505024, out + 5505024, t);
}

// ---------------------------------------------------------------------------
// Weight prep: w_adapt[o][C][ky][kx] -> bf16 hi/lo in [l][o][K], K = k*256+C.
// ---------------------------------------------------------------------------
__global__ void wprep_kernel(const float* __restrict__ w0, const float* __restrict__ w1,
                             const float* __restrict__ w2, const float* __restrict__ w3) {
    int l = blockIdx.y;
    const float* src = (l == 0) ? w0 : (l == 1) ? w1 : (l == 2) ? w2 : w3;
    int idx = blockIdx.x * 256 + threadIdx.x;     // [0, 294912)
    int o = idx / 1152, j = idx - o * 1152;
    int K0 = 2 * j, K1 = K0 + 1;
    int k0 = K0 >> 8, C0 = K0 & 255;
    int k1 = K1 >> 8, C1 = K1 & 255;
    float a = src[o * 2304 + C0 * 9 + k0];
    float b = src[o * 2304 + C1 * 9 + k1];
    __nv_bfloat16 ah = __float2bfloat16_rn(a);
    __nv_bfloat16 bh = __float2bfloat16_rn(b);
    __nv_bfloat16 al = __float2bfloat16_rn(a - __bfloat162float(ah));
    __nv_bfloat16 bl = __float2bfloat16_rn(b - __bfloat162float(bh));
    size_t d = (size_t)l * 294912 + idx;
    g_wh[d] = ((unsigned)__bfloat16_as_ushort(bh) << 16) | __bfloat16_as_ushort(ah);
    g_wl[d] = ((unsigned)__bfloat16_as_ushort(bl) << 16) | __bfloat16_as_ushort(al);
}

// ---------------------------------------------------------------------------
// corr_all: warp per flat (level, b, pix). 256-thread blocks (8 warps);
// level boundaries (8192/2048/512/128) all divisible by 8.
// ---------------------------------------------------------------------------
template<int S, int D, int ST, int PD, int K2, int SP>
__device__ __forceinline__ void corr_one(int wloc, int lane,
                                         const float* __restrict__ xtb,
                                         float* __restrict__ corrb) {
    constexpr int P = S * S;
    int b = wloc / P, pix = wloc - b * P;
    int h = pix / S, w = pix - h * S;

    const float4* f1 = reinterpret_cast<const float4*>(
        xtb + ((size_t)(2 + b) * P + pix) * 256 + lane * 8);
    float4 u0 = f1[0], u1 = f1[1];
    const float* f2b = xtb + (size_t)b * P * 256;
    float* cw = corrb + (size_t)wloc * SP;

    int s = 0;
    for (int iy = 0; iy < D; iy++) {
        int py = h - PD + iy * ST;
        for (int ix = 0; ix < D; ix++, s++) {
            int px = w - PD + ix * ST;
            float v = 0.f;
            if ((unsigned)py < (unsigned)S && (unsigned)px < (unsigned)S) {
                const float4* f2 = reinterpret_cast<const float4*>(
                    f2b + ((size_t)py * S + px) * 256 + lane * 8);
                float4 q0 = f2[0], q1 = f2[1];
                v = u0.x * q0.x + u0.y * q0.y + u0.z * q0.z + u0.w * q0.w +
                    u1.x * q1.x + u1.y * q1.y + u1.z * q1.z + u1.w * q1.w;
            }
            v += __shfl_xor_sync(0xffffffffu, v, 16);
            v += __shfl_xor_sync(0xffffffffu, v, 8);
            v += __shfl_xor_sync(0xffffffffu, v, 4);
            v += __shfl_xor_sync(0xffffffffu, v, 2);
            v += __shfl_xor_sync(0xffffffffu, v, 1);
            if (lane == 0) cw[s] = v * (1.f / 256.f);
        }
    }
    for (int z = K2 + lane; z < SP; z += 32) cw[z] = 0.f;
}

__global__ void corr_all() {
    int w = (blockIdx.x * blockDim.x + threadIdx.x) >> 5;
    int lane = threadIdx.x & 31;
    if (w < 8192)       corr_one<64, 17, 2, 16, 289, 320>(w,         lane, g_xt,           g_corr);
    else if (w < 10240) corr_one<32, 17, 1,  8, 289, 320>(w - 8192,  lane, g_xt + 4194304, g_corr + 2621440);
    else if (w < 10752) corr_one<16,  9, 1,  4,  81,  96>(w - 10240, lane, g_xt + 5242880, g_corr + 3276800);
    else                corr_one< 8,  5, 1,  2,  25,  32>(w - 10752, lane, g_xt + 5505024, g_corr + 3325952);
}

// ---------------------------------------------------------------------------
// offset_all: block = 64 flat pixels x 72 outputs, 288 threads, 170 blocks.
// Shared arrays hoisted to the kernel so all template instantiations share
// ONE allocation (3 instantiations x 17664B blew the 48KB static limit).
// ---------------------------------------------------------------------------
template<int K2, int SP>
__device__ __forceinline__ void offset_one(const float* __restrict__ w_off,
                                           const float* __restrict__ corrb,
                                           int local, int flatpb,
                                           float (*Ws)[73], float (*Cs)[65]) {
    int tid = threadIdx.x;
    int og = tid >> 4, pg = tid & 15;
    int pb = local * 64;

    float acc[4][4];
#pragma unroll
    for (int j = 0; j < 4; j++)
#pragma unroll
        for (int i = 0; i < 4; i++) acc[j][i] = 0.f;

    int wo = tid >> 2;
    int ws0 = (tid & 3) * 8;

    for (int cs = 0; cs < SP; cs += 32) {
#pragma unroll
        for (int u = 0; u < 8; u++) {
            int s = ws0 + u;
            int gs = cs + s;
            Ws[s][wo] = (gs < K2) ? w_off[(size_t)wo * K2 + gs] : 0.f;
        }
        for (int idx = tid; idx < 512; idx += 288) {
            int px = idx & 63, s4 = idx >> 6;
            float4 v = *reinterpret_cast<const float4*>(
                corrb + (size_t)(pb + px) * SP + cs + s4 * 4);
            Cs[s4 * 4 + 0][px] = v.x;
            Cs[s4 * 4 + 1][px] = v.y;
            Cs[s4 * 4 + 2][px] = v.z;
            Cs[s4 * 4 + 3][px] = v.w;
        }
        __syncthreads();
#pragma unroll 4
        for (int s = 0; s < 32; s++) {
            float c0 = Cs[s][pg];
            float c1 = Cs[s][pg + 16];
            float c2 = Cs[s][pg + 32];
            float c3 = Cs[s][pg + 48];
#pragma unroll
            for (int j = 0; j < 4; j++) {
                float wv = Ws[s][og * 4 + j];
                acc[j][0] = fmaf(wv, c0, acc[j][0]);
                acc[j][1] = fmaf(wv, c1, acc[j][1]);
                acc[j][2] = fmaf(wv, c2, acc[j][2]);
                acc[j][3] = fmaf(wv, c3, acc[j][3]);
            }
        }
        __syncthreads();
    }
#pragma unroll
    for (int i = 0; i < 4; i++)
#pragma unroll
        for (int j = 0; j < 4; j++)
            g_off[(size_t)(flatpb + pg + 16 * i) * 72 + og * 4 + j] = acc[j][i];
}

__global__ void __launch_bounds__(288) offset_all(
    const float* __restrict__ wo0, const float* __restrict__ wo1,
    const float* __restrict__ wo2, const float* __restrict__ wo3) {
    __shared__ float Ws[32][73];
    __shared__ float Cs[32][65];
    int id = blockIdx.x;
    if (id < 128)      offset_one<289, 320>(wo0, g_corr,           id,       id * 64,              Ws, Cs);
    else if (id < 160) offset_one<289, 320>(wo1, g_corr + 2621440, id - 128, 8192  + (id - 128) * 64, Ws, Cs);
    else if (id < 168) offset_one< 81,  96>(wo2, g_corr + 3276800, id - 160, 10240 + (id - 160) * 64, Ws, Cs);
    else               offset_one< 25,  32>(wo3, g_corr + 3325952, id - 168, 10752 + (id - 168) * 64, Ws, Cs);
}

// ---------------------------------------------------------------------------
// im2col_all: warp per flat pixel; g_off/g_col indexed by flat id directly.
// ---------------------------------------------------------------------------
template<int S>
__device__ __forceinline__ void im2col_one(int wflat, int wloc, int lane,
                                           const float* __restrict__ xtb) {
    constexpr int P = S * S;
    int b = wloc / P, pix = wloc - b * P;
    int h = pix / S, w = pix - h * S;

    const float* op = g_off + (size_t)wflat * 72;
    const float* xi = xtb + (size_t)(2 + b) * P * 256;
    size_t rowb = (size_t)wflat * 1152;

    for (int q = 0; q < 36; q++) {
        int g = q / 9, k = q - g * 9;
        int ky = k / 3, kx = k - ky * 3;
        float fy = (float)(h + ky - 1) + op[q * 2];
        float fx = (float)(w + kx - 1) + op[q * 2 + 1];
        float fy0 = floorf(fy), fx0 = floorf(fx);
        float wy = fy - fy0, wx = fx - fx0;
        int y0 = (int)fy0, x0 = (int)fx0;
        float w00 = (1.f - wy) * (1.f - wx);
        float w01 = (1.f - wy) * wx;
        float w10 = wy * (1.f - wx);
        float w11 = wy * wx;
        bool vy0 = (unsigned)y0 < (unsigned)S, vy1 = (unsigned)(y0 + 1) < (unsigned)S;
        bool vx0 = (unsigned)x0 < (unsigned)S, vx1 = (unsigned)(x0 + 1) < (unsigned)S;
        bool v00 = vy0 && vx0, v01 = vy0 && vx1, v10 = vy1 && vx0, v11 = vy1 && vx1;

        const float* xc = xi + g * 64 + lane * 2;
        int i00 = (y0 * S + x0) * 256;
        float a0 = 0.f, a1 = 0.f;
        if (v00) { float2 u = *(const float2*)(xc + i00);
                   a0 += w00 * u.x; a1 += w00 * u.y; }
        if (v01) { float2 u = *(const float2*)(xc + i00 + 256);
                   a0 += w01 * u.x; a1 += w01 * u.y; }
        if (v10) { float2 u = *(const float2*)(xc + i00 + S * 256);
                   a0 += w10 * u.x; a1 += w10 * u.y; }
        if (v11) { float2 u = *(const float2*)(xc + i00 + S * 256 + 256);
                   a0 += w11 * u.x; a1 += w11 * u.y; }

        __nv_bfloat16 h0 = __float2bfloat16_rn(a0);
        __nv_bfloat16 h1 = __float2bfloat16_rn(a1);
        __nv_bfloat16 l0 = __float2bfloat16_rn(a0 - __bfloat162float(h0));
        __nv_bfloat16 l1 = __float2bfloat16_rn(a1 - __bfloat162float(h1));
        size_t d = rowb + k * 128 + g * 32 + lane;
        g_colh[d] = ((unsigned)__bfloat16_as_ushort(h1) << 16) | __bfloat16_as_ushort(h0);
        g_coll[d] = ((unsigned)__bfloat16_as_ushort(l1) << 16) | __bfloat16_as_ushort(l0);
    }
}

__global__ void im2col_all() {
    int w = (blockIdx.x * blockDim.x + threadIdx.x) >> 5;
    int lane = threadIdx.x & 31;
    if (w < 8192)       im2col_one<64>(w, w,         lane, g_xt);
    else if (w < 10240) im2col_one<32>(w, w - 8192,  lane, g_xt + 4194304);
    else if (w < 10752) im2col_one<16>(w, w - 10240, lane, g_xt + 5242880);
    else                im2col_one< 8>(w, w - 10752, lane, g_xt + 5505024);
}

// ---------------------------------------------------------------------------
// mma.sync bf16 GEMM, 3-term split. CTA 128(M) x 64(N), 8 warps (32x32 each).
// K-chunks of 64 bf16, double-buffered cp.async. Rows padded to 72 bf16.
// grid (170, 2), block 256.
// ---------------------------------------------------------------------------
#define ST_SIZE 55296
#define OFF_AH  0
#define OFF_AL  18432
#define OFF_BH  36864
#define OFF_BL  46080
#define GEMM_SMEM 110592

__global__ void __launch_bounds__(256) gemm_mma(float* __restrict__ out) {
    extern __shared__ __align__(128) char smem[];
    uint32_t sb = smem_u32(smem);
    int tid = threadIdx.x;
    int lane = tid & 31, warp = tid >> 5;
    int warp_m = warp & 3, warp_n = warp >> 2;   // 4 x 2 warps

    int t = blockIdx.x, m0 = blockIdx.y * 128;
    int L, f, HW, OB, PBL;
    if (t < 128)      { L = 0; f = t * 64;         HW = 4096; OB = 0;       PBL = 0;     }
    else if (t < 160) { L = 1; f = (t - 128) * 64; HW = 1024; OB = 4194304; PBL = 8192;  }
    else if (t < 168) { L = 2; f = (t - 160) * 64; HW = 256;  OB = 5242880; PBL = 10240; }
    else              { L = 3; f = (t - 168) * 64; HW = 64;   OB = 5505024; PBL = 10752; }
    int p0 = PBL + f;
    int b = f / HW, pix = f - b * HW;

    const unsigned* GAh = g_wh + (size_t)(L * 256 + m0) * 1152;
    const unsigned* GAl = g_wl + (size_t)(L * 256 + m0) * 1152;
    const unsigned* GBh = g_colh + (size_t)p0 * 1152;
    const unsigned* GBl = g_coll + (size_t)p0 * 1152;

    auto stage = [&](int ci, int buf) {
        uint32_t base = sb + buf * ST_SIZE;
        int kc = ci * 32;
#pragma unroll
        for (int i = 0; i < 4; i++) {
            int u = i * 256 + tid;
            int r = u >> 3, c = u & 7;
            uint32_t so = (uint32_t)(r * 144 + c * 16);
            CPA16(base + OFF_AH + so, GAh + (size_t)r * 1152 + kc + c * 4);
            CPA16(base + OFF_AL + so, GAl + (size_t)r * 1152 + kc + c * 4);
        }
#pragma unroll
        for (int i = 0; i < 2; i++) {
            int u = i * 256 + tid;
            int r = u >> 3, c = u & 7;
            uint32_t so = (uint32_t)(r * 144 + c * 16);
            CPA16(base + OFF_BH + so, GBh + (size_t)r * 1152 + kc + c * 4);
            CPA16(base + OFF_BL + so, GBl + (size_t)r * 1152 + kc + c * 4);
        }
    };

    float acc[2][4][4];
#pragma unroll
    for (int am = 0; am < 2; am++)
#pragma unroll
        for (int an = 0; an < 4; an++)
#pragma unroll
            for (int i = 0; i < 4; i++) acc[am][an][i] = 0.f;

    uint32_t a_row = (uint32_t)(warp_m * 32 + (lane & 15));
    uint32_t a_koff = (uint32_t)((lane >> 4) * 16);
    uint32_t b_row = (uint32_t)(warp_n * 32 + (lane & 7) + ((lane >> 4) << 3));
    uint32_t b_koff = (uint32_t)(((lane >> 3) & 1) * 16);

    stage(0, 0);
    CPA_COMMIT();

    for (int ci = 0; ci < 36; ci++) {
        if (ci + 1 < 36) {
            stage(ci + 1, (ci + 1) & 1);
            CPA_COMMIT();
            CPA_WAIT1();
        } else {
            CPA_WAIT0();
        }
        __syncthreads();
        uint32_t base = sb + (ci & 1) * ST_SIZE;
#pragma unroll
        for (int ks = 0; ks < 4; ks++) {
            uint32_t ao = a_row * 144 + (uint32_t)(ks * 32) + a_koff;
            uint32_t bo = b_row * 144 + (uint32_t)(ks * 32) + b_koff;
            uint32_t ah0[4], ah1[4], al0[4], al1[4];
            uint32_t bh0[4], bh1[4], bl0[4], bl1[4];
            LDSM4(ah0, base + OFF_AH + ao);
            LDSM4(ah1, base + OFF_AH + ao + 16 * 144);
            LDSM4(al0, base + OFF_AL + ao);
            LDSM4(al1, base + OFF_AL + ao + 16 * 144);
            LDSM4(bh0, base + OFF_BH + bo);
            LDSM4(bh1, base + OFF_BH + bo + 16 * 144);
            LDSM4(bl0, base + OFF_BL + bo);
            LDSM4(bl1, base + OFF_BL + bo + 16 * 144);

            MMA16816(acc[0][0], ah0, bh0[0], bh0[1]);
            MMA16816(acc[0][1], ah0, bh0[2], bh0[3]);
            MMA16816(acc[0][2], ah0, bh1[0], bh1[1]);
            MMA16816(acc[0][3], ah0, bh1[2], bh1[3]);
            MMA16816(acc[1][0], ah1, bh0[0], bh0[1]);
            MMA16816(acc[1][1], ah1, bh0[2], bh0[3]);
            MMA16816(acc[1][2], ah1, bh1[0], bh1[1]);
            MMA16816(acc[1][3], ah1, bh1[2], bh1[3]);

            MMA16816(acc[0][0], ah0, bl0[0], bl0[1]);
            MMA16816(acc[0][1], ah0, bl0[2], bl0[3]);
            MMA16816(acc[0][2], ah0, bl1[0], bl1[1]);
            MMA16816(acc[0][3], ah0, bl1[2], bl1[3]);
            MMA16816(acc[1][0], ah1, bl0[0], bl0[1]);
            MMA16816(acc[1][1], ah1, bl0[2], bl0[3]);
            MMA16816(acc[1][2], ah1, bl1[0], bl1[1]);
            MMA16816(acc[1][3], ah1, bl1[2], bl1[3]);

            MMA16816(acc[0][0], al0, bh0[0], bh0[1]);
            MMA16816(acc[0][1], al0, bh0[2], bh0[3]);
            MMA16816(acc[0][2], al0, bh1[0], bh1[1]);
            MMA16816(acc[0][3], al0, bh1[2], bh1[3]);
            MMA16816(acc[1][0], al1, bh0[0], bh0[1]);
            MMA16816(acc[1][1], al1, bh0[2], bh0[3]);
            MMA16816(acc[1][2], al1, bh1[0], bh1[1]);
            MMA16816(acc[1][3], al1, bh1[2], bh1[3]);
        }
        __syncthreads();
    }

    float* Ob = out + OB + ((size_t)(2 + b) * 256) * HW + pix;
#pragma unroll
    for (int am = 0; am < 2; am++) {
        int o = m0 + warp_m * 32 + am * 16 + (lane >> 2);
#pragma unroll
        for (int an = 0; an < 4; an++) {
            int c = warp_n * 32 + an * 8 + (lane & 3) * 2;
            float2 v0 = make_float2(fmaxf(acc[am][an][0], 0.f),
                                    fmaxf(acc[am][an][1], 0.f));
            float2 v1 = make_float2(fmaxf(acc[am][an][2], 0.f),
                                    fmaxf(acc[am][an][3], 0.f));
            *reinterpret_cast<float2*>(Ob + (size_t)o * HW + c) = v0;
            *reinterpret_cast<float2*>(Ob + (size_t)(o + 8) * HW + c) = v1;
        }
    }
}

extern "C" void kernel_launch(void* const* d_in, const int* in_sizes, int n_in,
                              void* d_out, int out_size) {
    // Runtime input classification by element count (metadata interleaves
    // w_off{i}/w_adapt{i} — do NOT trust signature order).
    const float* xs[4]   = {0, 0, 0, 0};
    const float* wofs[4] = {0, 0, 0, 0};
    const float* wads[4] = {0, 0, 0, 0};
    int n_adapt = 0, n_off_big = 0;
    for (int i = 0; i < n_in; i++) {
        const float* p = (const float*)d_in[i];
        switch (in_sizes[i]) {
            case 4194304: xs[0] = p; break;
            case 1048576: xs[1] = p; break;
            case 262144:  xs[2] = p; break;
            case 65536:   xs[3] = p; break;
            case 589824:  wads[n_adapt++] = p; break;
            case 20808:   wofs[n_off_big++] = p; break;
            case 5832:    wofs[2] = p; break;
            case 1800:    wofs[3] = p; break;
            default: break;
        }
    }
    float* out = (float*)d_out;

    cudaFuncSetAttribute(gemm_mma, cudaFuncAttributeMaxDynamicSharedMemorySize,
                         GEMM_SMEM);

    wprep_kernel<<<dim3(1152, 4), 256>>>(wads[0], wads[1], wads[2], wads[3]);
    transpose_all<<<5440, dim3(32, 8)>>>(xs[0], xs[1], xs[2], xs[3], out);
    corr_all<<<1360, 256>>>();
    offset_all<<<170, 288>>>(wofs[0], wofs[1], wofs[2], wofs[3]);
    im2col_all<<<1360, 256>>>();
    gemm_mma<<<dim3(170, 2), 256, GEMM_SMEM>>>(out);
}